// round 7
// baseline (speedup 1.0000x reference)
#include <cuda_runtime.h>
#include <cstdint>

#define T_TOKENS 16384
#define DIMX     2048
#define NE       8
#define KSEL     2048

// libdevice exp — exact bits, immune to fast-math flags.
extern "C" __device__ float __nv_expf(float);

// Scratch: per-expert sort keys (key = ~bits(sigmoid(logit))) and a global
// 16-bit histogram of keys per expert (level 0 of the radix select).
__device__ unsigned int g_keys[NE * T_TOKENS];
__device__ unsigned int g_hist[NE * 65536];

// ---------------------------------------------------------------------------
// Kernel 1: logits + keys + global key-histogram.
// Block = 32-token tile x all 8 experts. Warp = 32 DISTINCT tokens x one
// expert-pair: x-LDS.128 moves 512B unique per instruction (zero crossbar
// waste), W reads are warp-uniform __ldg (L1-resident, off the crossbar).
// Each thread: 2 in-order scalar fma.rn chains (bitwise identical to R4-R6).
// ---------------------------------------------------------------------------
#define K1T   128
#define TILE  32
#define CH    32
#define XP    36   // pitch: lane*36 floats -> lane mod 8 bank-quads, conflict-free

__global__ void __launch_bounds__(K1T) k1_gemv(const float* __restrict__ x,
                                               const float* __restrict__ W)
{
    __shared__ float sx[TILE * XP + 4];

    const int tid  = threadIdx.x;
    const int lane = tid & 31;
    const int wp   = tid >> 5;        // warp = expert pair 0..3
    const int e0   = wp * 2, e1 = e0 + 1;
    const size_t rowBase = (size_t)blockIdx.x * TILE;

    // Staging: 32 tokens x 32 dims = 256 float4, 2 per thread (coalesced).
    const int r0 = tid >> 3,          c0 = tid & 7;
    const int r1 = (tid + K1T) >> 3,  c1 = (tid + K1T) & 7;

    float4 p0, p1;
    {
        const float* xb = x + rowBase * DIMX;
        p0 = *reinterpret_cast<const float4*>(xb + (size_t)r0 * DIMX + c0 * 4);
        p1 = *reinterpret_cast<const float4*>(xb + (size_t)r1 * DIMX + c1 * 4);
    }

    float a0 = 0.0f, a1 = 0.0f;
    const float4* w0r = reinterpret_cast<const float4*>(W + e0 * DIMX);
    const float4* w1r = reinterpret_cast<const float4*>(W + e1 * DIMX);

    for (int ch = 0; ch < DIMX / CH; ++ch) {
        __syncthreads();
        *reinterpret_cast<float4*>(&sx[r0 * XP + c0 * 4]) = p0;
        *reinterpret_cast<float4*>(&sx[r1 * XP + c1 * 4]) = p1;
        __syncthreads();

        if (ch + 1 < DIMX / CH) {
            const float* xb = x + rowBase * DIMX + (ch + 1) * CH;
            p0 = *reinterpret_cast<const float4*>(xb + (size_t)r0 * DIMX + c0 * 4);
            p1 = *reinterpret_cast<const float4*>(xb + (size_t)r1 * DIMX + c1 * 4);
        }

        const float* xd = sx + lane * XP;
#pragma unroll
        for (int g = 0; g < CH / 4; ++g) {
            float4 xv  = *reinterpret_cast<const float4*>(xd + g * 4);
            float4 wv0 = __ldg(w0r + ch * (CH / 4) + g);   // warp-uniform
            float4 wv1 = __ldg(w1r + ch * (CH / 4) + g);   // warp-uniform
            a0 = __fmaf_rn(xv.x, wv0.x, a0);
            a0 = __fmaf_rn(xv.y, wv0.y, a0);
            a0 = __fmaf_rn(xv.z, wv0.z, a0);
            a0 = __fmaf_rn(xv.w, wv0.w, a0);
            a1 = __fmaf_rn(xv.x, wv1.x, a1);
            a1 = __fmaf_rn(xv.y, wv1.y, a1);
            a1 = __fmaf_rn(xv.z, wv1.z, a1);
            a1 = __fmaf_rn(xv.w, wv1.w, a1);
        }
    }

    // sigmoid (exp form, bit-matched) -> monotone descending key
    const int token = (int)rowBase + lane;
    float em0 = __nv_expf(-a0);
    float s0  = __fdiv_rn(1.0f, __fadd_rn(1.0f, em0));
    unsigned key0 = ~__float_as_uint(s0);
    float em1 = __nv_expf(-a1);
    float s1  = __fdiv_rn(1.0f, __fadd_rn(1.0f, em1));
    unsigned key1 = ~__float_as_uint(s1);

    g_keys[e0 * T_TOKENS + token] = key0;
    g_keys[e1 * T_TOKENS + token] = key1;

    // global 16-bit histogram (level 0 of select), warp-aggregated
    unsigned h0 = (unsigned)e0 * 65536u + (key0 >> 16);
    unsigned m0 = __match_any_sync(0xffffffffu, h0);
    if ((int)lane == __ffs(m0) - 1) atomicAdd(&g_hist[h0], (unsigned)__popc(m0));
    unsigned h1 = (unsigned)e1 * 65536u + (key1 >> 16);
    unsigned m1 = __match_any_sync(0xffffffffu, h1);
    if ((int)lane == __ffs(m1) - 1) atomicAdd(&g_hist[h1], (unsigned)__popc(m1));
}

// ---------------------------------------------------------------------------
// Kernel 2: per-expert exact top-2048 (desc, ties -> lower index).
// 46-bit key K = (key32 << 14) | token. Level 0 = global 16-bit histogram;
// boundary-bin candidates collected and warp-sorted (<=64, the common case);
// fallback radix levels for m>64. Two-pass atomic-free final collect;
// hybrid bitonic sort (smem j>=64, shfl j<=32).
// ---------------------------------------------------------------------------
#define K2_THREADS 1024
#define HC         4
#define MASK46     ((1ull << 46) - 1)

__global__ void __launch_bounds__(K2_THREADS) k2_topk(float* __restrict__ out, int writeIdx)
{
    extern __shared__ unsigned char sm2[];
    unsigned int*        hist  = reinterpret_cast<unsigned int*>(sm2);              // HC x 4096 (64KB)
    unsigned int*        hscan = reinterpret_cast<unsigned int*>(sm2 + 65536);      // 4096 (16KB)
    unsigned long long*  sel   = reinterpret_cast<unsigned long long*>(sm2 + 81920);  // 2048 u64
    unsigned long long*  cand  = reinterpret_cast<unsigned long long*>(sm2 + 98304);  // 2048 u64

    __shared__ unsigned int s_wsum[32];
    __shared__ unsigned long long s_pref;
    __shared__ unsigned long long s_mask;
    __shared__ unsigned long long s_kstar;
    __shared__ int          s_want;
    __shared__ int          s_bin;
    __shared__ unsigned int s_before;
    __shared__ int          s_exact;
    __shared__ int          s_n;

    const int e    = blockIdx.x;
    const int tid  = threadIdx.x;
    const unsigned lane = tid & 31;
    const int wid  = tid >> 5;

    // Keys in registers: kreg[r] = key of token (tid + r*1024).
    unsigned kreg[16];
    {
        const unsigned* gk = g_keys + e * T_TOKENS;
#pragma unroll
        for (int r = 0; r < 16; ++r)
            kreg[r] = gk[tid + r * K2_THREADS];
    }

    if (tid == 0) { s_exact = 0; s_n = 0; }
    __syncthreads();

    // ---- Level 0: scan global 16-bit histogram, find boundary bin ----
    {
        const uint4* gh = reinterpret_cast<const uint4*>(g_hist + e * 65536);
        unsigned lsum = 0;
#pragma unroll
        for (int q = 0; q < 16; ++q) {
            uint4 u = gh[tid * 16 + q];
            lsum += u.x + u.y + u.z + u.w;
        }
        unsigned si = lsum;
#pragma unroll
        for (int o = 1; o < 32; o <<= 1) {
            unsigned n = __shfl_up_sync(0xffffffffu, si, o);
            if (lane >= (unsigned)o) si += n;
        }
        if (lane == 31) s_wsum[wid] = si;
        __syncthreads();
        if (wid == 0) {
            unsigned w = s_wsum[lane];
            unsigned wi = w;
#pragma unroll
            for (int o = 1; o < 32; o <<= 1) {
                unsigned n = __shfl_up_sync(0xffffffffu, wi, o);
                if (lane >= (unsigned)o) wi += n;
            }
            s_wsum[lane] = wi - w;
        }
        __syncthreads();
        unsigned base = s_wsum[wid] + (si - lsum);
        if ((int)base < KSEL && (int)(base + lsum) >= KSEL) {
            const unsigned* gb = g_hist + e * 65536 + tid * 64;
            unsigned run = base;
            for (int j = 0; j < 64; ++j) {
                unsigned c = gb[j];
                if ((int)run < KSEL && (int)(run + c) >= KSEL) {
                    s_bin = tid * 64 + j;
                    s_before = run;
                    if ((int)(run + c) == KSEL) s_exact = 1;
                    break;
                }
                run += c;
            }
        }
        __syncthreads();
        if (tid == 0) {
            s_want = KSEL - (int)s_before;
            s_pref = (unsigned long long)(unsigned)s_bin << 30;
            s_mask = 0xFFFFull << 30;
        }
        __syncthreads();
    }

    unsigned long long Kstar;
    if (s_exact) {
        Kstar = s_pref | ((1ull << 30) - 1);
    } else {
        // Collect boundary-bin candidates.
        const unsigned binv = (unsigned)s_bin;
#pragma unroll
        for (int r = 0; r < 16; ++r) {
            bool c = ((kreg[r] >> 16) == binv);
            unsigned bal = __ballot_sync(0xffffffffu, c);
            int base = 0;
            if (lane == 0 && bal) base = atomicAdd(&s_n, __popc(bal));
            base = __shfl_sync(0xffffffffu, base, 0);
            if (c) {
                int pos = base + __popc(bal & ((1u << lane) - 1u));
                if (pos < 2048)
                    cand[pos] = ((unsigned long long)kreg[r] << 14)
                              | (unsigned)(tid + r * K2_THREADS);
            }
        }
        __syncthreads();
        const int m = s_n;
        const int want = s_want;

        if (m <= 64) {
            // One-warp bitonic sort of <=64 candidates via shfl.
            if (wid == 0) {
                unsigned long long a = (lane < (unsigned)m) ? cand[lane] : ~0ull;
                unsigned long long b = (lane + 32 < (unsigned)m) ? cand[lane + 32] : ~0ull;
                const int g0 = (int)lane, g1 = (int)lane + 32;
                for (int k = 2; k <= 64; k <<= 1) {
                    for (int j = k >> 1; j >= 1; j >>= 1) {
                        if (j == 32) {
                            bool asc = ((g0 & k) == 0);
                            if ((a > b) == asc) { unsigned long long t = a; a = b; b = t; }
                        } else {
                            unsigned long long pa = __shfl_xor_sync(0xffffffffu, a, j);
                            unsigned long long pb = __shfl_xor_sync(0xffffffffu, b, j);
                            bool lower = ((lane & (unsigned)j) == 0u);
                            bool ascA  = ((g0 & k) == 0);
                            bool ascB  = ((g1 & k) == 0);
                            unsigned long long amin = (a < pa) ? a : pa;
                            unsigned long long amax = (a < pa) ? pa : a;
                            unsigned long long bmin = (b < pb) ? b : pb;
                            unsigned long long bmax = (b < pb) ? pb : b;
                            a = (lower == ascA) ? amin : amax;
                            b = (lower == ascB) ? bmin : bmax;
                        }
                    }
                }
                int idx = want - 1;
                unsigned long long va = __shfl_sync(0xffffffffu, a, idx & 31);
                unsigned long long vb = __shfl_sync(0xffffffffu, b, idx & 31);
                if (lane == 0) s_kstar = (idx < 32) ? va : vb;
            }
            __syncthreads();
            Kstar = s_kstar;
        } else {
            // Fallback: in-block radix levels over register keys.
            const int shifts[3] = {18, 6, 0};
            const int nbits [3] = {12, 12, 6};
            for (int lvl = 0; lvl < 3; ++lvl) {
                const int shift = shifts[lvl];
                const int nb    = 1 << nbits[lvl];
                const int wantLoc              = s_want;
                const unsigned long long mask  = s_mask;
                const unsigned long long pref  = s_pref;

                for (int i = tid; i < HC * 4096; i += K2_THREADS) hist[i] = 0u;
                __syncthreads();

                unsigned int* myhist = hist + (wid & (HC - 1)) * 4096;
#pragma unroll
                for (int r = 0; r < 16; ++r) {
                    unsigned long long K = ((unsigned long long)kreg[r] << 14)
                                         | (unsigned)(tid + r * K2_THREADS);
                    bool mm = ((K & mask) == pref);
                    unsigned active = __ballot_sync(0xffffffffu, mm);
                    if (mm) {
                        int bin = (int)((K >> shift) & (unsigned)(nb - 1));
                        unsigned same = __match_any_sync(active, bin);
                        if ((int)lane == (__ffs(same) - 1))
                            atomicAdd(&myhist[bin], (unsigned)__popc(same));
                    }
                }
                __syncthreads();
                {
                    unsigned v[4];
                    unsigned sthr = 0;
#pragma unroll
                    for (int j = 0; j < 4; ++j) {
                        int b = 4 * tid + j;
                        unsigned t = 0;
#pragma unroll
                        for (int c = 0; c < HC; ++c) t += hist[c * 4096 + b];
                        v[j] = t; sthr += t;
                    }
                    unsigned si = sthr;
#pragma unroll
                    for (int o = 1; o < 32; o <<= 1) {
                        unsigned n = __shfl_up_sync(0xffffffffu, si, o);
                        if (lane >= (unsigned)o) si += n;
                    }
                    if (lane == 31) s_wsum[wid] = si;
                    __syncthreads();
                    if (wid == 0) {
                        unsigned w = s_wsum[lane];
                        unsigned wi = w;
#pragma unroll
                        for (int o = 1; o < 32; o <<= 1) {
                            unsigned n = __shfl_up_sync(0xffffffffu, wi, o);
                            if (lane >= (unsigned)o) wi += n;
                        }
                        s_wsum[lane] = wi - w;
                    }
                    __syncthreads();
                    unsigned run = s_wsum[wid] + (si - sthr);
#pragma unroll
                    for (int j = 0; j < 4; ++j) {
                        run += v[j];
                        hscan[4 * tid + j] = run;
                    }
                }
                __syncthreads();
                for (int i = tid; i < nb; i += K2_THREADS) {
                    unsigned c = hscan[i];
                    unsigned p = (i > 0) ? hscan[i - 1] : 0u;
                    if ((int)c >= wantLoc && (int)p < wantLoc) {
                        s_bin = i; s_before = p;
                        if ((int)c == wantLoc) s_exact = 1;
                    }
                }
                __syncthreads();
                if (tid == 0) {
                    s_want = wantLoc - (int)s_before;
                    s_pref = pref | ((unsigned long long)(unsigned)s_bin << shift);
                    s_mask = mask | ((unsigned long long)(unsigned)(nb - 1) << shift);
                }
                __syncthreads();
                if (s_exact) break;
            }
            Kstar = s_pref | (~s_mask & MASK46);
        }
    }

    // ---- Final collect: exactly 2048 keys <= Kstar (atomic-free two-pass) ----
    {
        int cw = 0;
#pragma unroll
        for (int r = 0; r < 16; ++r) {
            unsigned long long K = ((unsigned long long)kreg[r] << 14)
                                 | (unsigned)(tid + r * K2_THREADS);
            unsigned bal = __ballot_sync(0xffffffffu, K <= Kstar);
            cw += __popc(bal);
        }
        if (lane == 0) s_wsum[wid] = (unsigned)cw;
        __syncthreads();
        if (wid == 0) {
            unsigned w = s_wsum[lane];
            unsigned wi = w;
#pragma unroll
            for (int o = 1; o < 32; o <<= 1) {
                unsigned n = __shfl_up_sync(0xffffffffu, wi, o);
                if (lane >= (unsigned)o) wi += n;
            }
            s_wsum[lane] = wi - w;   // exclusive per-warp base
        }
        __syncthreads();
        int base = (int)s_wsum[wid];
#pragma unroll
        for (int r = 0; r < 16; ++r) {
            unsigned long long K = ((unsigned long long)kreg[r] << 14)
                                 | (unsigned)(tid + r * K2_THREADS);
            bool take = (K <= Kstar);
            unsigned bal = __ballot_sync(0xffffffffu, take);
            if (take) {
                int pos = base + __popc(bal & ((1u << lane) - 1u));
                sel[pos] = K;
            }
            base += __popc(bal);
        }
    }
    __syncthreads();

    // ---- Hybrid bitonic sort ascending over sel[2048] ----
    const int g0 = (wid << 6) | (int)lane;
    const int g1 = g0 + 32;
    unsigned long long a = sel[g0];
    unsigned long long b = sel[g1];

    for (int k = 2; k <= KSEL; k <<= 1) {
        int j = k >> 1;
        if (j >= 64) {
            sel[g0] = a; sel[g1] = b;
            __syncthreads();
            for (; j >= 64; j >>= 1) {
                int i = ((tid & ~(j - 1)) << 1) | (tid & (j - 1));
                int l = i | j;
                unsigned long long u = sel[i];
                unsigned long long v = sel[l];
                bool asc = ((i & k) == 0);
                if ((u > v) == asc) { sel[i] = v; sel[l] = u; }
                __syncthreads();
            }
            a = sel[g0]; b = sel[g1];   // j == 32 now
        }
        for (; j >= 1; j >>= 1) {
            if (j == 32) {
                bool asc = ((g0 & k) == 0);
                if ((a > b) == asc) { unsigned long long t = a; a = b; b = t; }
            } else {
                unsigned long long pa = __shfl_xor_sync(0xffffffffu, a, j);
                unsigned long long pb = __shfl_xor_sync(0xffffffffu, b, j);
                bool lower = ((lane & (unsigned)j) == 0u);
                bool ascA  = ((g0 & k) == 0);
                bool ascB  = ((g1 & k) == 0);
                unsigned long long amin = (a < pa) ? a : pa;
                unsigned long long amax = (a < pa) ? pa : a;
                unsigned long long bmin = (b < pb) ? b : pb;
                unsigned long long bmax = (b < pb) ? pb : b;
                a = (lower == ascA) ? amin : amax;
                b = (lower == ascB) ? bmin : bmax;
            }
        }
    }

    // Emit from registers.
    {
        float scA = __uint_as_float(~(unsigned)(a >> 14));
        float scB = __uint_as_float(~(unsigned)(b >> 14));
        out[e * KSEL + g0] = scA;
        out[e * KSEL + g1] = scB;
        if (writeIdx) {
            out[NE * KSEL + e * KSEL + g0] = (float)(unsigned)(a & 0x3FFFu);
            out[NE * KSEL + e * KSEL + g1] = (float)(unsigned)(b & 0x3FFFu);
        }
    }
}

// ---------------------------------------------------------------------------
extern "C" void kernel_launch(void* const* d_in, const int* in_sizes, int n_in,
                              void* d_out, int out_size)
{
    const float* x = (const float*)d_in[0];   // [16384, 2048] f32
    const float* W = (const float*)d_in[1];   // [8, 2048] f32
    float* out = (float*)d_out;

    const int SMEM2 = 65536 + 16384 + 16384 + 16384;  // 114688

    cudaFuncSetAttribute(k2_topk, cudaFuncAttributeMaxDynamicSharedMemorySize, SMEM2);

    void* hp = nullptr;
    cudaGetSymbolAddress(&hp, g_hist);
    cudaMemsetAsync(hp, 0, sizeof(unsigned) * NE * 65536);

    const int writeIdx = (out_size >= 2 * NE * KSEL) ? 1 : 0;

    k1_gemv<<<T_TOKENS / TILE, K1T>>>(x, W);
    k2_topk<<<NE, K2_THREADS, SMEM2>>>(out, writeIdx);
}

// round 8
// speedup vs baseline: 1.3561x; 1.3561x over previous
#include <cuda_runtime.h>
#include <cstdint>

#define T_TOKENS 16384
#define DIMX     2048
#define NE       8
#define KSEL     2048

// libdevice exp — exact bits, immune to fast-math flags.
extern "C" __device__ float __nv_expf(float);

// Scratch: per-expert sort keys (key = ~bits(sigmoid(logit))) and a global
// 16-bit histogram of keys per expert (level 0 of the radix select).
__device__ unsigned int g_keys[NE * T_TOKENS];
__device__ unsigned int g_hist[NE * 65536];

// ---------------------------------------------------------------------------
// Kernel 0: zero the global histogram (replaces cudaMemsetAsync; also makes
// launch parity such that ncu's skip-5 capture lands on k1).
// ---------------------------------------------------------------------------
__global__ void k0_zero()
{
    uint4* p = reinterpret_cast<uint4*>(g_hist);
    p[blockIdx.x * 1024 + threadIdx.x] = make_uint4(0u, 0u, 0u, 0u);
}

__global__ void k_dummy() {}

// ---------------------------------------------------------------------------
// Kernel 1: logits + keys + global key-histogram.
// Block = 64-token tile, 4 warps; warp = expert-pair P, lanes = 32 tokens x 2
// (tokens L and L+32). Thread runs 4 independent in-order scalar fma.rn
// chains (tokens {L, L+32} x experts {2P, 2P+1}) — bitwise identical to the
// passing kernels. x via LDS.128 (every 512B unique -> crossbar-optimal);
// W via per-lane registers + shfl broadcast (off the crossbar and LSU).
// ---------------------------------------------------------------------------
#define K1T   128
#define TILE  64
#define CH    32
#define XP    36   // pitch floats: 144B rows -> 16B aligned, 4-phase optimal

__global__ void __launch_bounds__(K1T) k1_gemv(const float* __restrict__ x,
                                               const float* __restrict__ W)
{
    __shared__ float sx[2][TILE * XP];

    const int tid  = threadIdx.x;
    const int lane = tid & 31;
    const int P    = tid >> 5;            // expert pair 0..3
    const int e0   = 2 * P, e1 = e0 + 1;
    const size_t rowBase = (size_t)blockIdx.x * TILE;

    // Staging assignment: 64 rows x 8 float4-cols per chunk; 4 float4/thread.
    int rr[4], cc[4];
#pragma unroll
    for (int k = 0; k < 4; ++k) {
        int idx = tid + k * K1T;
        rr[k] = idx >> 3;
        cc[k] = idx & 7;
    }

    const float* xb = x + rowBase * DIMX;

    // Prologue: load chunk 0, store to buf 0; prefetch chunk 1; W chunk 0.
    float4 pf[4];
#pragma unroll
    for (int k = 0; k < 4; ++k)
        pf[k] = *reinterpret_cast<const float4*>(xb + (size_t)rr[k] * DIMX + cc[k] * 4);
#pragma unroll
    for (int k = 0; k < 4; ++k)
        *reinterpret_cast<float4*>(&sx[0][rr[k] * XP + cc[k] * 4]) = pf[k];
#pragma unroll
    for (int k = 0; k < 4; ++k)
        pf[k] = *reinterpret_cast<const float4*>(xb + (size_t)rr[k] * DIMX + CH + cc[k] * 4);

    float wx = W[e0 * DIMX + lane];       // W chunk 0, this lane's dim slot
    float wy = W[e1 * DIMX + lane];

    float a00 = 0.0f, a01 = 0.0f, a10 = 0.0f, a11 = 0.0f;

    __syncthreads();   // buf0 staged

    for (int ch = 0; ch < DIMX / CH; ++ch) {
        const int cur = ch & 1;

        // Stage chunk ch+1 into the other buffer (visible after loop-end sync).
        if (ch + 1 < DIMX / CH) {
#pragma unroll
            for (int k = 0; k < 4; ++k)
                *reinterpret_cast<float4*>(&sx[cur ^ 1][rr[k] * XP + cc[k] * 4]) = pf[k];
        }
        // Prefetch chunk ch+2 from DRAM.
        if (ch + 2 < DIMX / CH) {
            const float* xc = xb + (ch + 2) * CH;
#pragma unroll
            for (int k = 0; k < 4; ++k)
                pf[k] = *reinterpret_cast<const float4*>(xc + (size_t)rr[k] * DIMX + cc[k] * 4);
        }
        // Prefetch W for chunk ch+1 (L1-resident, coalesced).
        float wxn = wx, wyn = wy;
        if (ch + 1 < DIMX / CH) {
            wxn = W[e0 * DIMX + (ch + 1) * CH + lane];
            wyn = W[e1 * DIMX + (ch + 1) * CH + lane];
        }

        // Compute chunk ch: 8 groups of 4 dims.
        const float* x0p = &sx[cur][lane * XP];
        const float* x1p = &sx[cur][(lane + 32) * XP];
#pragma unroll
        for (int g = 0; g < CH / 4; ++g) {
            float4 x0 = *reinterpret_cast<const float4*>(x0p + g * 4);
            float4 x1 = *reinterpret_cast<const float4*>(x1p + g * 4);
#pragma unroll
            for (int j = 0; j < 4; ++j) {
                float w0 = __shfl_sync(0xffffffffu, wx, g * 4 + j);
                float w1 = __shfl_sync(0xffffffffu, wy, g * 4 + j);
                float xs0 = (j == 0) ? x0.x : (j == 1) ? x0.y : (j == 2) ? x0.z : x0.w;
                float xs1 = (j == 0) ? x1.x : (j == 1) ? x1.y : (j == 2) ? x1.z : x1.w;
                a00 = __fmaf_rn(xs0, w0, a00);
                a01 = __fmaf_rn(xs0, w1, a01);
                a10 = __fmaf_rn(xs1, w0, a10);
                a11 = __fmaf_rn(xs1, w1, a11);
            }
        }
        wx = wxn; wy = wyn;
        __syncthreads();
    }

    // sigmoid (exp form, bit-matched) -> monotone descending key; emit 4.
    const int t0 = (int)rowBase + lane;
    const int t1 = t0 + 32;
    float acc[4] = {a00, a01, a10, a11};
    const int eid[4] = {e0, e1, e0, e1};
    const int tok[4] = {t0, t0, t1, t1};
#pragma unroll
    for (int u = 0; u < 4; ++u) {
        float em = __nv_expf(-acc[u]);
        float s  = __fdiv_rn(1.0f, __fadd_rn(1.0f, em));
        unsigned key = ~__float_as_uint(s);
        g_keys[eid[u] * T_TOKENS + tok[u]] = key;
        unsigned h = (unsigned)eid[u] * 65536u + (key >> 16);
        unsigned m = __match_any_sync(0xffffffffu, h);
        if ((int)lane == __ffs(m) - 1)
            atomicAdd(&g_hist[h], (unsigned)__popc(m));
    }
}

// ---------------------------------------------------------------------------
// Kernel 2: per-expert exact top-2048 (desc, ties -> lower index).
// (unchanged from R7 — passing)
// ---------------------------------------------------------------------------
#define K2_THREADS 1024
#define HC         4
#define MASK46     ((1ull << 46) - 1)

__global__ void __launch_bounds__(K2_THREADS) k2_topk(float* __restrict__ out, int writeIdx)
{
    extern __shared__ unsigned char sm2[];
    unsigned int*        hist  = reinterpret_cast<unsigned int*>(sm2);
    unsigned int*        hscan = reinterpret_cast<unsigned int*>(sm2 + 65536);
    unsigned long long*  sel   = reinterpret_cast<unsigned long long*>(sm2 + 81920);
    unsigned long long*  cand  = reinterpret_cast<unsigned long long*>(sm2 + 98304);

    __shared__ unsigned int s_wsum[32];
    __shared__ unsigned long long s_pref;
    __shared__ unsigned long long s_mask;
    __shared__ unsigned long long s_kstar;
    __shared__ int          s_want;
    __shared__ int          s_bin;
    __shared__ unsigned int s_before;
    __shared__ int          s_exact;
    __shared__ int          s_n;

    const int e    = blockIdx.x;
    const int tid  = threadIdx.x;
    const unsigned lane = tid & 31;
    const int wid  = tid >> 5;

    unsigned kreg[16];
    {
        const unsigned* gk = g_keys + e * T_TOKENS;
#pragma unroll
        for (int r = 0; r < 16; ++r)
            kreg[r] = gk[tid + r * K2_THREADS];
    }

    if (tid == 0) { s_exact = 0; s_n = 0; }
    __syncthreads();

    // ---- Level 0: scan global 16-bit histogram ----
    {
        const uint4* gh = reinterpret_cast<const uint4*>(g_hist + e * 65536);
        unsigned lsum = 0;
#pragma unroll
        for (int q = 0; q < 16; ++q) {
            uint4 u = gh[tid * 16 + q];
            lsum += u.x + u.y + u.z + u.w;
        }
        unsigned si = lsum;
#pragma unroll
        for (int o = 1; o < 32; o <<= 1) {
            unsigned n = __shfl_up_sync(0xffffffffu, si, o);
            if (lane >= (unsigned)o) si += n;
        }
        if (lane == 31) s_wsum[wid] = si;
        __syncthreads();
        if (wid == 0) {
            unsigned w = s_wsum[lane];
            unsigned wi = w;
#pragma unroll
            for (int o = 1; o < 32; o <<= 1) {
                unsigned n = __shfl_up_sync(0xffffffffu, wi, o);
                if (lane >= (unsigned)o) wi += n;
            }
            s_wsum[lane] = wi - w;
        }
        __syncthreads();
        unsigned base = s_wsum[wid] + (si - lsum);
        if ((int)base < KSEL && (int)(base + lsum) >= KSEL) {
            const unsigned* gb = g_hist + e * 65536 + tid * 64;
            unsigned run = base;
            for (int j = 0; j < 64; ++j) {
                unsigned c = gb[j];
                if ((int)run < KSEL && (int)(run + c) >= KSEL) {
                    s_bin = tid * 64 + j;
                    s_before = run;
                    if ((int)(run + c) == KSEL) s_exact = 1;
                    break;
                }
                run += c;
            }
        }
        __syncthreads();
        if (tid == 0) {
            s_want = KSEL - (int)s_before;
            s_pref = (unsigned long long)(unsigned)s_bin << 30;
            s_mask = 0xFFFFull << 30;
        }
        __syncthreads();
    }

    unsigned long long Kstar;
    if (s_exact) {
        Kstar = s_pref | ((1ull << 30) - 1);
    } else {
        const unsigned binv = (unsigned)s_bin;
#pragma unroll
        for (int r = 0; r < 16; ++r) {
            bool c = ((kreg[r] >> 16) == binv);
            unsigned bal = __ballot_sync(0xffffffffu, c);
            int base = 0;
            if (lane == 0 && bal) base = atomicAdd(&s_n, __popc(bal));
            base = __shfl_sync(0xffffffffu, base, 0);
            if (c) {
                int pos = base + __popc(bal & ((1u << lane) - 1u));
                if (pos < 2048)
                    cand[pos] = ((unsigned long long)kreg[r] << 14)
                              | (unsigned)(tid + r * K2_THREADS);
            }
        }
        __syncthreads();
        const int m = s_n;
        const int want = s_want;

        if (m <= 64) {
            if (wid == 0) {
                unsigned long long a = (lane < (unsigned)m) ? cand[lane] : ~0ull;
                unsigned long long b = (lane + 32 < (unsigned)m) ? cand[lane + 32] : ~0ull;
                const int g0 = (int)lane, g1 = (int)lane + 32;
                for (int k = 2; k <= 64; k <<= 1) {
                    for (int j = k >> 1; j >= 1; j >>= 1) {
                        if (j == 32) {
                            bool asc = ((g0 & k) == 0);
                            if ((a > b) == asc) { unsigned long long t = a; a = b; b = t; }
                        } else {
                            unsigned long long pa = __shfl_xor_sync(0xffffffffu, a, j);
                            unsigned long long pb = __shfl_xor_sync(0xffffffffu, b, j);
                            bool lower = ((lane & (unsigned)j) == 0u);
                            bool ascA  = ((g0 & k) == 0);
                            bool ascB  = ((g1 & k) == 0);
                            unsigned long long amin = (a < pa) ? a : pa;
                            unsigned long long amax = (a < pa) ? pa : a;
                            unsigned long long bmin = (b < pb) ? b : pb;
                            unsigned long long bmax = (b < pb) ? pb : b;
                            a = (lower == ascA) ? amin : amax;
                            b = (lower == ascB) ? bmin : bmax;
                        }
                    }
                }
                int idx = want - 1;
                unsigned long long va = __shfl_sync(0xffffffffu, a, idx & 31);
                unsigned long long vb = __shfl_sync(0xffffffffu, b, idx & 31);
                if (lane == 0) s_kstar = (idx < 32) ? va : vb;
            }
            __syncthreads();
            Kstar = s_kstar;
        } else {
            const int shifts[3] = {18, 6, 0};
            const int nbits [3] = {12, 12, 6};
            for (int lvl = 0; lvl < 3; ++lvl) {
                const int shift = shifts[lvl];
                const int nb    = 1 << nbits[lvl];
                const int wantLoc              = s_want;
                const unsigned long long mask  = s_mask;
                const unsigned long long pref  = s_pref;

                for (int i = tid; i < HC * 4096; i += K2_THREADS) hist[i] = 0u;
                __syncthreads();

                unsigned int* myhist = hist + (wid & (HC - 1)) * 4096;
#pragma unroll
                for (int r = 0; r < 16; ++r) {
                    unsigned long long K = ((unsigned long long)kreg[r] << 14)
                                         | (unsigned)(tid + r * K2_THREADS);
                    bool mm = ((K & mask) == pref);
                    unsigned active = __ballot_sync(0xffffffffu, mm);
                    if (mm) {
                        int bin = (int)((K >> shift) & (unsigned)(nb - 1));
                        unsigned same = __match_any_sync(active, bin);
                        if ((int)lane == (__ffs(same) - 1))
                            atomicAdd(&myhist[bin], (unsigned)__popc(same));
                    }
                }
                __syncthreads();
                {
                    unsigned v[4];
                    unsigned sthr = 0;
#pragma unroll
                    for (int j = 0; j < 4; ++j) {
                        int b = 4 * tid + j;
                        unsigned t = 0;
#pragma unroll
                        for (int c = 0; c < HC; ++c) t += hist[c * 4096 + b];
                        v[j] = t; sthr += t;
                    }
                    unsigned si = sthr;
#pragma unroll
                    for (int o = 1; o < 32; o <<= 1) {
                        unsigned n = __shfl_up_sync(0xffffffffu, si, o);
                        if (lane >= (unsigned)o) si += n;
                    }
                    if (lane == 31) s_wsum[wid] = si;
                    __syncthreads();
                    if (wid == 0) {
                        unsigned w = s_wsum[lane];
                        unsigned wi = w;
#pragma unroll
                        for (int o = 1; o < 32; o <<= 1) {
                            unsigned n = __shfl_up_sync(0xffffffffu, wi, o);
                            if (lane >= (unsigned)o) wi += n;
                        }
                        s_wsum[lane] = wi - w;
                    }
                    __syncthreads();
                    unsigned run = s_wsum[wid] + (si - sthr);
#pragma unroll
                    for (int j = 0; j < 4; ++j) {
                        run += v[j];
                        hscan[4 * tid + j] = run;
                    }
                }
                __syncthreads();
                for (int i = tid; i < nb; i += K2_THREADS) {
                    unsigned c = hscan[i];
                    unsigned p = (i > 0) ? hscan[i - 1] : 0u;
                    if ((int)c >= wantLoc && (int)p < wantLoc) {
                        s_bin = i; s_before = p;
                        if ((int)c == wantLoc) s_exact = 1;
                    }
                }
                __syncthreads();
                if (tid == 0) {
                    s_want = wantLoc - (int)s_before;
                    s_pref = pref | ((unsigned long long)(unsigned)s_bin << shift);
                    s_mask = mask | ((unsigned long long)(unsigned)(nb - 1) << shift);
                }
                __syncthreads();
                if (s_exact) break;
            }
            Kstar = s_pref | (~s_mask & MASK46);
        }
    }

    // ---- Final collect (atomic-free two-pass) ----
    {
        int cw = 0;
#pragma unroll
        for (int r = 0; r < 16; ++r) {
            unsigned long long K = ((unsigned long long)kreg[r] << 14)
                                 | (unsigned)(tid + r * K2_THREADS);
            unsigned bal = __ballot_sync(0xffffffffu, K <= Kstar);
            cw += __popc(bal);
        }
        if (lane == 0) s_wsum[wid] = (unsigned)cw;
        __syncthreads();
        if (wid == 0) {
            unsigned w = s_wsum[lane];
            unsigned wi = w;
#pragma unroll
            for (int o = 1; o < 32; o <<= 1) {
                unsigned n = __shfl_up_sync(0xffffffffu, wi, o);
                if (lane >= (unsigned)o) wi += n;
            }
            s_wsum[lane] = wi - w;
        }
        __syncthreads();
        int base = (int)s_wsum[wid];
#pragma unroll
        for (int r = 0; r < 16; ++r) {
            unsigned long long K = ((unsigned long long)kreg[r] << 14)
                                 | (unsigned)(tid + r * K2_THREADS);
            bool take = (K <= Kstar);
            unsigned bal = __ballot_sync(0xffffffffu, take);
            if (take) {
                int pos = base + __popc(bal & ((1u << lane) - 1u));
                sel[pos] = K;
            }
            base += __popc(bal);
        }
    }
    __syncthreads();

    // ---- Hybrid bitonic sort ascending over sel[2048] ----
    const int g0 = (wid << 6) | (int)lane;
    const int g1 = g0 + 32;
    unsigned long long a = sel[g0];
    unsigned long long b = sel[g1];

    for (int k = 2; k <= KSEL; k <<= 1) {
        int j = k >> 1;
        if (j >= 64) {
            sel[g0] = a; sel[g1] = b;
            __syncthreads();
            for (; j >= 64; j >>= 1) {
                int i = ((tid & ~(j - 1)) << 1) | (tid & (j - 1));
                int l = i | j;
                unsigned long long u = sel[i];
                unsigned long long v = sel[l];
                bool asc = ((i & k) == 0);
                if ((u > v) == asc) { sel[i] = v; sel[l] = u; }
                __syncthreads();
            }
            a = sel[g0]; b = sel[g1];
        }
        for (; j >= 1; j >>= 1) {
            if (j == 32) {
                bool asc = ((g0 & k) == 0);
                if ((a > b) == asc) { unsigned long long t = a; a = b; b = t; }
            } else {
                unsigned long long pa = __shfl_xor_sync(0xffffffffu, a, j);
                unsigned long long pb = __shfl_xor_sync(0xffffffffu, b, j);
                bool lower = ((lane & (unsigned)j) == 0u);
                bool ascA  = ((g0 & k) == 0);
                bool ascB  = ((g1 & k) == 0);
                unsigned long long amin = (a < pa) ? a : pa;
                unsigned long long amax = (a < pa) ? pa : a;
                unsigned long long bmin = (b < pb) ? b : pb;
                unsigned long long bmax = (b < pb) ? pb : b;
                a = (lower == ascA) ? amin : amax;
                b = (lower == ascB) ? bmin : bmax;
            }
        }
    }

    {
        float scA = __uint_as_float(~(unsigned)(a >> 14));
        float scB = __uint_as_float(~(unsigned)(b >> 14));
        out[e * KSEL + g0] = scA;
        out[e * KSEL + g1] = scB;
        if (writeIdx) {
            out[NE * KSEL + e * KSEL + g0] = (float)(unsigned)(a & 0x3FFFu);
            out[NE * KSEL + e * KSEL + g1] = (float)(unsigned)(b & 0x3FFFu);
        }
    }
}

// ---------------------------------------------------------------------------
extern "C" void kernel_launch(void* const* d_in, const int* in_sizes, int n_in,
                              void* d_out, int out_size)
{
    const float* x = (const float*)d_in[0];   // [16384, 2048] f32
    const float* W = (const float*)d_in[1];   // [8, 2048] f32
    float* out = (float*)d_out;

    const int SMEM2 = 65536 + 16384 + 16384 + 16384;  // 114688
    cudaFuncSetAttribute(k2_topk, cudaFuncAttributeMaxDynamicSharedMemorySize, SMEM2);

    const int writeIdx = (out_size >= 2 * NE * KSEL) ? 1 : 0;

    k0_zero<<<NE * 65536 / 4096, 1024>>>();                 // zero g_hist
    k1_gemv<<<T_TOKENS / TILE, K1T>>>(x, W);                // logits + keys + hist
    k2_topk<<<NE, K2_THREADS, SMEM2>>>(out, writeIdx);      // select + sort
    k_dummy<<<1, 1>>>();                                    // parity: ncu slot 6 = k1
}

// round 9
// speedup vs baseline: 1.4470x; 1.0671x over previous
#include <cuda_runtime.h>
#include <cstdint>

#define T_TOKENS 16384
#define DIMX     2048
#define NE       8
#define KSEL     2048

// libdevice exp — exact bits, immune to fast-math flags.
extern "C" __device__ float __nv_expf(float);

// Scratch: per-expert sort keys (key = ~bits(sigmoid(logit))) and a global
// 16-bit histogram of keys per expert (level 0 of the radix select).
// g_hist is zero at module load and re-zeroed by k2 every call (replay-safe).
__device__ unsigned int g_keys[NE * T_TOKENS];
__device__ unsigned int g_hist[NE * 65536];

// ---------------------------------------------------------------------------
// Kernel 1: logits + keys + global key-histogram.
// Block = 64-token tile, 4 warps; warp = expert-pair P; lanes = tokens L,L+32.
// Thread: 4 independent in-order scalar fma.rn chains (bitwise identical to
// all passing rounds). x via LDS.128 (512B unique -> 4-cyc optimal);
// W via BROADCAST LDS.64 of interleaved expert-pairs (~1 cyc, replaces R8's
// shfl which burned 4 cyc/op on the same crossbar pipe).
// ---------------------------------------------------------------------------
#define K1T    128
#define TILE   64
#define CH     32
#define XP     36                 // 144B rows: 16B aligned, 4-phase LDS.128
#define WPP    4100               // per-pair pitch (floats): 2*2048 + 4 pad

__global__ void __launch_bounds__(K1T) k1_gemv(const float* __restrict__ x,
                                               const float* __restrict__ W)
{
    extern __shared__ float sm[];
    float* swp = sm;                         // [4][WPP]  interleaved pairs, 65.6KB
    float* sx  = sm + 4 * WPP;               // [2][TILE*XP] double buffer, 18.4KB

    const int tid  = threadIdx.x;
    const int lane = tid & 31;
    const int P    = tid >> 5;               // expert pair 0..3
    const int e0   = 2 * P, e1 = e0 + 1;
    const size_t rowBase = (size_t)blockIdx.x * TILE;

    // Stage W pair P interleaved: swp[P][d*2+0]=W[e0][d], [d*2+1]=W[e1][d].
    {
        const float4* W0 = reinterpret_cast<const float4*>(W + e0 * DIMX);
        const float4* W1 = reinterpret_cast<const float4*>(W + e1 * DIMX);
        float* dst = swp + P * WPP;
#pragma unroll
        for (int it = 0; it < DIMX / 4 / 32; ++it) {
            int d4 = it * 32 + lane;          // float4 index; d = 4*d4
            float4 w0 = W0[d4];
            float4 w1 = W1[d4];
            float2* dp = reinterpret_cast<float2*>(dst + d4 * 8);
            dp[0] = make_float2(w0.x, w1.x);
            dp[1] = make_float2(w0.y, w1.y);
            dp[2] = make_float2(w0.z, w1.z);
            dp[3] = make_float2(w0.w, w1.w);
        }
    }

    // x staging assignment: 64 rows x 8 float4-cols per 32-dim chunk.
    int rr[4], cc[4];
#pragma unroll
    for (int k = 0; k < 4; ++k) {
        int idx = tid + k * K1T;
        rr[k] = idx >> 3;
        cc[k] = idx & 7;
    }

    const float* xb = x + rowBase * DIMX;

    // Prologue: chunk 0 -> buf0; prefetch chunk 1.
    float4 pf[4];
#pragma unroll
    for (int k = 0; k < 4; ++k)
        pf[k] = *reinterpret_cast<const float4*>(xb + (size_t)rr[k] * DIMX + cc[k] * 4);
#pragma unroll
    for (int k = 0; k < 4; ++k)
        *reinterpret_cast<float4*>(&sx[rr[k] * XP + cc[k] * 4]) = pf[k];
#pragma unroll
    for (int k = 0; k < 4; ++k)
        pf[k] = *reinterpret_cast<const float4*>(xb + (size_t)rr[k] * DIMX + CH + cc[k] * 4);

    float a00 = 0.0f, a01 = 0.0f, a10 = 0.0f, a11 = 0.0f;

    __syncthreads();   // buf0 + swp staged

    const float* wb0 = swp + P * WPP;

    for (int ch = 0; ch < DIMX / CH; ++ch) {
        const int cur = ch & 1;

        if (ch + 1 < DIMX / CH) {             // stage chunk ch+1 into other buf
#pragma unroll
            for (int k = 0; k < 4; ++k)
                *reinterpret_cast<float4*>(
                    &sx[(cur ^ 1) * (TILE * XP) + rr[k] * XP + cc[k] * 4]) = pf[k];
        }
        if (ch + 2 < DIMX / CH) {             // prefetch chunk ch+2 from DRAM
            const float* xc = xb + (ch + 2) * CH;
#pragma unroll
            for (int k = 0; k < 4; ++k)
                pf[k] = *reinterpret_cast<const float4*>(xc + (size_t)rr[k] * DIMX + cc[k] * 4);
        }

        // Compute chunk ch: 8 groups x 4 dims; w via broadcast LDS.64.
        const float* x0p = sx + cur * (TILE * XP) + lane * XP;
        const float* x1p = x0p + 32 * XP;
        const float* wb  = wb0 + ch * (CH * 2);
#pragma unroll
        for (int g = 0; g < CH / 4; ++g) {
            float4 x0 = *reinterpret_cast<const float4*>(x0p + g * 4);
            float4 x1 = *reinterpret_cast<const float4*>(x1p + g * 4);
            float2 wA = *reinterpret_cast<const float2*>(wb + g * 8 + 0);
            float2 wB = *reinterpret_cast<const float2*>(wb + g * 8 + 2);
            float2 wC = *reinterpret_cast<const float2*>(wb + g * 8 + 4);
            float2 wD = *reinterpret_cast<const float2*>(wb + g * 8 + 6);
            a00 = __fmaf_rn(x0.x, wA.x, a00);  a01 = __fmaf_rn(x0.x, wA.y, a01);
            a10 = __fmaf_rn(x1.x, wA.x, a10);  a11 = __fmaf_rn(x1.x, wA.y, a11);
            a00 = __fmaf_rn(x0.y, wB.x, a00);  a01 = __fmaf_rn(x0.y, wB.y, a01);
            a10 = __fmaf_rn(x1.y, wB.x, a10);  a11 = __fmaf_rn(x1.y, wB.y, a11);
            a00 = __fmaf_rn(x0.z, wC.x, a00);  a01 = __fmaf_rn(x0.z, wC.y, a01);
            a10 = __fmaf_rn(x1.z, wC.x, a10);  a11 = __fmaf_rn(x1.z, wC.y, a11);
            a00 = __fmaf_rn(x0.w, wD.x, a00);  a01 = __fmaf_rn(x0.w, wD.y, a01);
            a10 = __fmaf_rn(x1.w, wD.x, a10);  a11 = __fmaf_rn(x1.w, wD.y, a11);
        }
        __syncthreads();
    }

    // sigmoid (exp form, bit-matched) -> monotone descending key; emit 4.
    const int t0 = (int)rowBase + lane;
    const int t1 = t0 + 32;
    float acc[4] = {a00, a01, a10, a11};
    const int eid[4] = {e0, e1, e0, e1};
    const int tok[4] = {t0, t0, t1, t1};
#pragma unroll
    for (int u = 0; u < 4; ++u) {
        float em = __nv_expf(-acc[u]);
        float s  = __fdiv_rn(1.0f, __fadd_rn(1.0f, em));
        unsigned key = ~__float_as_uint(s);
        g_keys[eid[u] * T_TOKENS + tok[u]] = key;
        unsigned h = (unsigned)eid[u] * 65536u + (key >> 16);
        unsigned m = __match_any_sync(0xffffffffu, h);
        if ((int)lane == __ffs(m) - 1)
            atomicAdd(&g_hist[h], (unsigned)__popc(m));
    }
}

// ---------------------------------------------------------------------------
// Kernel 2: per-expert exact top-2048 (desc, ties -> lower index).
// Level 0 = global 16-bit histogram; boundary-bin candidates warp-sorted
// (m<=64 common case) or 3 fallback radix levels; atomic-free collect;
// hybrid bitonic sort. Re-zeroes its g_hist slice at the end.
// ---------------------------------------------------------------------------
#define K2_THREADS 1024
#define HC         4
#define MASK46     ((1ull << 46) - 1)

__global__ void __launch_bounds__(K2_THREADS) k2_topk(float* __restrict__ out, int writeIdx)
{
    extern __shared__ unsigned char sm2[];
    unsigned int*        hist  = reinterpret_cast<unsigned int*>(sm2);
    unsigned int*        hscan = reinterpret_cast<unsigned int*>(sm2 + 65536);
    unsigned long long*  sel   = reinterpret_cast<unsigned long long*>(sm2 + 81920);
    unsigned long long*  cand  = reinterpret_cast<unsigned long long*>(sm2 + 98304);

    __shared__ unsigned int s_wsum[32];
    __shared__ unsigned long long s_pref;
    __shared__ unsigned long long s_mask;
    __shared__ unsigned long long s_kstar;
    __shared__ int          s_want;
    __shared__ int          s_bin;
    __shared__ unsigned int s_before;
    __shared__ int          s_exact;
    __shared__ int          s_n;

    const int e    = blockIdx.x;
    const int tid  = threadIdx.x;
    const unsigned lane = tid & 31;
    const int wid  = tid >> 5;

    unsigned kreg[16];
    {
        const unsigned* gk = g_keys + e * T_TOKENS;
#pragma unroll
        for (int r = 0; r < 16; ++r)
            kreg[r] = gk[tid + r * K2_THREADS];
    }

    if (tid == 0) { s_exact = 0; s_n = 0; }
    __syncthreads();

    // ---- Level 0: scan global 16-bit histogram ----
    {
        const uint4* gh = reinterpret_cast<const uint4*>(g_hist + e * 65536);
        unsigned lsum = 0;
#pragma unroll
        for (int q = 0; q < 16; ++q) {
            uint4 u = gh[tid * 16 + q];
            lsum += u.x + u.y + u.z + u.w;
        }
        unsigned si = lsum;
#pragma unroll
        for (int o = 1; o < 32; o <<= 1) {
            unsigned n = __shfl_up_sync(0xffffffffu, si, o);
            if (lane >= (unsigned)o) si += n;
        }
        if (lane == 31) s_wsum[wid] = si;
        __syncthreads();
        if (wid == 0) {
            unsigned w = s_wsum[lane];
            unsigned wi = w;
#pragma unroll
            for (int o = 1; o < 32; o <<= 1) {
                unsigned n = __shfl_up_sync(0xffffffffu, wi, o);
                if (lane >= (unsigned)o) wi += n;
            }
            s_wsum[lane] = wi - w;
        }
        __syncthreads();
        unsigned base = s_wsum[wid] + (si - lsum);
        if ((int)base < KSEL && (int)(base + lsum) >= KSEL) {
            const unsigned* gb = g_hist + e * 65536 + tid * 64;
            unsigned run = base;
            for (int j = 0; j < 64; ++j) {
                unsigned c = gb[j];
                if ((int)run < KSEL && (int)(run + c) >= KSEL) {
                    s_bin = tid * 64 + j;
                    s_before = run;
                    if ((int)(run + c) == KSEL) s_exact = 1;
                    break;
                }
                run += c;
            }
        }
        __syncthreads();
        if (tid == 0) {
            s_want = KSEL - (int)s_before;
            s_pref = (unsigned long long)(unsigned)s_bin << 30;
            s_mask = 0xFFFFull << 30;
        }
        __syncthreads();
    }

    unsigned long long Kstar;
    if (s_exact) {
        Kstar = s_pref | ((1ull << 30) - 1);
    } else {
        const unsigned binv = (unsigned)s_bin;
#pragma unroll
        for (int r = 0; r < 16; ++r) {
            bool c = ((kreg[r] >> 16) == binv);
            unsigned bal = __ballot_sync(0xffffffffu, c);
            int base = 0;
            if (lane == 0 && bal) base = atomicAdd(&s_n, __popc(bal));
            base = __shfl_sync(0xffffffffu, base, 0);
            if (c) {
                int pos = base + __popc(bal & ((1u << lane) - 1u));
                if (pos < 2048)
                    cand[pos] = ((unsigned long long)kreg[r] << 14)
                              | (unsigned)(tid + r * K2_THREADS);
            }
        }
        __syncthreads();
        const int m = s_n;
        const int want = s_want;

        if (m <= 64) {
            if (wid == 0) {
                unsigned long long a = (lane < (unsigned)m) ? cand[lane] : ~0ull;
                unsigned long long b = (lane + 32 < (unsigned)m) ? cand[lane + 32] : ~0ull;
                const int g0 = (int)lane, g1 = (int)lane + 32;
                for (int k = 2; k <= 64; k <<= 1) {
                    for (int j = k >> 1; j >= 1; j >>= 1) {
                        if (j == 32) {
                            bool asc = ((g0 & k) == 0);
                            if ((a > b) == asc) { unsigned long long t = a; a = b; b = t; }
                        } else {
                            unsigned long long pa = __shfl_xor_sync(0xffffffffu, a, j);
                            unsigned long long pb = __shfl_xor_sync(0xffffffffu, b, j);
                            bool lower = ((lane & (unsigned)j) == 0u);
                            bool ascA  = ((g0 & k) == 0);
                            bool ascB  = ((g1 & k) == 0);
                            unsigned long long amin = (a < pa) ? a : pa;
                            unsigned long long amax = (a < pa) ? pa : a;
                            unsigned long long bmin = (b < pb) ? b : pb;
                            unsigned long long bmax = (b < pb) ? pb : b;
                            a = (lower == ascA) ? amin : amax;
                            b = (lower == ascB) ? bmin : bmax;
                        }
                    }
                }
                int idx = want - 1;
                unsigned long long va = __shfl_sync(0xffffffffu, a, idx & 31);
                unsigned long long vb = __shfl_sync(0xffffffffu, b, idx & 31);
                if (lane == 0) s_kstar = (idx < 32) ? va : vb;
            }
            __syncthreads();
            Kstar = s_kstar;
        } else {
            const int shifts[3] = {18, 6, 0};
            const int nbits [3] = {12, 12, 6};
            for (int lvl = 0; lvl < 3; ++lvl) {
                const int shift = shifts[lvl];
                const int nb    = 1 << nbits[lvl];
                const int wantLoc              = s_want;
                const unsigned long long mask  = s_mask;
                const unsigned long long pref  = s_pref;

                for (int i = tid; i < HC * 4096; i += K2_THREADS) hist[i] = 0u;
                __syncthreads();

                unsigned int* myhist = hist + (wid & (HC - 1)) * 4096;
#pragma unroll
                for (int r = 0; r < 16; ++r) {
                    unsigned long long K = ((unsigned long long)kreg[r] << 14)
                                         | (unsigned)(tid + r * K2_THREADS);
                    bool mm = ((K & mask) == pref);
                    unsigned active = __ballot_sync(0xffffffffu, mm);
                    if (mm) {
                        int bin = (int)((K >> shift) & (unsigned)(nb - 1));
                        unsigned same = __match_any_sync(active, bin);
                        if ((int)lane == (__ffs(same) - 1))
                            atomicAdd(&myhist[bin], (unsigned)__popc(same));
                    }
                }
                __syncthreads();
                {
                    unsigned v[4];
                    unsigned sthr = 0;
#pragma unroll
                    for (int j = 0; j < 4; ++j) {
                        int b = 4 * tid + j;
                        unsigned t = 0;
#pragma unroll
                        for (int c = 0; c < HC; ++c) t += hist[c * 4096 + b];
                        v[j] = t; sthr += t;
                    }
                    unsigned si = sthr;
#pragma unroll
                    for (int o = 1; o < 32; o <<= 1) {
                        unsigned n = __shfl_up_sync(0xffffffffu, si, o);
                        if (lane >= (unsigned)o) si += n;
                    }
                    if (lane == 31) s_wsum[wid] = si;
                    __syncthreads();
                    if (wid == 0) {
                        unsigned w = s_wsum[lane];
                        unsigned wi = w;
#pragma unroll
                        for (int o = 1; o < 32; o <<= 1) {
                            unsigned n = __shfl_up_sync(0xffffffffu, wi, o);
                            if (lane >= (unsigned)o) wi += n;
                        }
                        s_wsum[lane] = wi - w;
                    }
                    __syncthreads();
                    unsigned run = s_wsum[wid] + (si - sthr);
#pragma unroll
                    for (int j = 0; j < 4; ++j) {
                        run += v[j];
                        hscan[4 * tid + j] = run;
                    }
                }
                __syncthreads();
                for (int i = tid; i < nb; i += K2_THREADS) {
                    unsigned c = hscan[i];
                    unsigned p = (i > 0) ? hscan[i - 1] : 0u;
                    if ((int)c >= wantLoc && (int)p < wantLoc) {
                        s_bin = i; s_before = p;
                        if ((int)c == wantLoc) s_exact = 1;
                    }
                }
                __syncthreads();
                if (tid == 0) {
                    s_want = wantLoc - (int)s_before;
                    s_pref = pref | ((unsigned long long)(unsigned)s_bin << shift);
                    s_mask = mask | ((unsigned long long)(unsigned)(nb - 1) << shift);
                }
                __syncthreads();
                if (s_exact) break;
            }
            Kstar = s_pref | (~s_mask & MASK46);
        }
    }

    // Re-zero this expert's g_hist slice (restores invariant for next call).
    {
        uint4 z = make_uint4(0u, 0u, 0u, 0u);
        uint4* gh = reinterpret_cast<uint4*>(g_hist + e * 65536);
        for (int i = tid; i < 65536 / 4; i += K2_THREADS) gh[i] = z;
    }

    // ---- Final collect (atomic-free two-pass) ----
    {
        int cw = 0;
#pragma unroll
        for (int r = 0; r < 16; ++r) {
            unsigned long long K = ((unsigned long long)kreg[r] << 14)
                                 | (unsigned)(tid + r * K2_THREADS);
            unsigned bal = __ballot_sync(0xffffffffu, K <= Kstar);
            cw += __popc(bal);
        }
        if (lane == 0) s_wsum[wid] = (unsigned)cw;
        __syncthreads();
        if (wid == 0) {
            unsigned w = s_wsum[lane];
            unsigned wi = w;
#pragma unroll
            for (int o = 1; o < 32; o <<= 1) {
                unsigned n = __shfl_up_sync(0xffffffffu, wi, o);
                if (lane >= (unsigned)o) wi += n;
            }
            s_wsum[lane] = wi - w;
        }
        __syncthreads();
        int base = (int)s_wsum[wid];
#pragma unroll
        for (int r = 0; r < 16; ++r) {
            unsigned long long K = ((unsigned long long)kreg[r] << 14)
                                 | (unsigned)(tid + r * K2_THREADS);
            bool take = (K <= Kstar);
            unsigned bal = __ballot_sync(0xffffffffu, take);
            if (take) {
                int pos = base + __popc(bal & ((1u << lane) - 1u));
                sel[pos] = K;
            }
            base += __popc(bal);
        }
    }
    __syncthreads();

    // ---- Hybrid bitonic sort ascending over sel[2048] ----
    const int g0 = (wid << 6) | (int)lane;
    const int g1 = g0 + 32;
    unsigned long long a = sel[g0];
    unsigned long long b = sel[g1];

    for (int k = 2; k <= KSEL; k <<= 1) {
        int j = k >> 1;
        if (j >= 64) {
            sel[g0] = a; sel[g1] = b;
            __syncthreads();
            for (; j >= 64; j >>= 1) {
                int i = ((tid & ~(j - 1)) << 1) | (tid & (j - 1));
                int l = i | j;
                unsigned long long u = sel[i];
                unsigned long long v = sel[l];
                bool asc = ((i & k) == 0);
                if ((u > v) == asc) { sel[i] = v; sel[l] = u; }
                __syncthreads();
            }
            a = sel[g0]; b = sel[g1];
        }
        for (; j >= 1; j >>= 1) {
            if (j == 32) {
                bool asc = ((g0 & k) == 0);
                if ((a > b) == asc) { unsigned long long t = a; a = b; b = t; }
            } else {
                unsigned long long pa = __shfl_xor_sync(0xffffffffu, a, j);
                unsigned long long pb = __shfl_xor_sync(0xffffffffu, b, j);
                bool lower = ((lane & (unsigned)j) == 0u);
                bool ascA  = ((g0 & k) == 0);
                bool ascB  = ((g1 & k) == 0);
                unsigned long long amin = (a < pa) ? a : pa;
                unsigned long long amax = (a < pa) ? pa : a;
                unsigned long long bmin = (b < pb) ? b : pb;
                unsigned long long bmax = (b < pb) ? pb : b;
                a = (lower == ascA) ? amin : amax;
                b = (lower == ascB) ? bmin : bmax;
            }
        }
    }

    {
        float scA = __uint_as_float(~(unsigned)(a >> 14));
        float scB = __uint_as_float(~(unsigned)(b >> 14));
        out[e * KSEL + g0] = scA;
        out[e * KSEL + g1] = scB;
        if (writeIdx) {
            out[NE * KSEL + e * KSEL + g0] = (float)(unsigned)(a & 0x3FFFu);
            out[NE * KSEL + e * KSEL + g1] = (float)(unsigned)(b & 0x3FFFu);
        }
    }
}

// ---------------------------------------------------------------------------
extern "C" void kernel_launch(void* const* d_in, const int* in_sizes, int n_in,
                              void* d_out, int out_size)
{
    const float* x = (const float*)d_in[0];   // [16384, 2048] f32
    const float* W = (const float*)d_in[1];   // [8, 2048] f32
    float* out = (float*)d_out;

    const int SMEM1 = (4 * WPP + 2 * TILE * XP) * (int)sizeof(float); // 84032
    const int SMEM2 = 65536 + 16384 + 16384 + 16384;                  // 114688

    cudaFuncSetAttribute(k1_gemv, cudaFuncAttributeMaxDynamicSharedMemorySize, SMEM1);
    cudaFuncSetAttribute(k2_topk, cudaFuncAttributeMaxDynamicSharedMemorySize, SMEM2);

    const int writeIdx = (out_size >= 2 * NE * KSEL) ? 1 : 0;

    k1_gemv<<<T_TOKENS / TILE, K1T, SMEM1>>>(x, W);
    k2_topk<<<NE, K2_THREADS, SMEM2>>>(out, writeIdx);
}

// round 10
// speedup vs baseline: 1.5529x; 1.0731x over previous
#include <cuda_runtime.h>
#include <cstdint>

#define T_TOKENS 16384
#define DIMX     2048
#define NE       8
#define KSEL     2048

// libdevice exp — exact bits, immune to fast-math flags.
extern "C" __device__ float __nv_expf(float);

// Scratch: per-expert sort keys (key = ~bits(sigmoid(logit))) and a global
// 14-bit histogram of keys per expert (level 0 of the radix select).
// g_hist is zero at module load and re-zeroed by k2 every call (replay-safe).
__device__ unsigned int g_keys[NE * T_TOKENS];
__device__ unsigned int g_hist[NE * 16384];

// ---------------------------------------------------------------------------
// Kernel 1: logits + keys + global key-histogram.
// Block = 64-token tile, 2 warps. Warp G handles experts 4G..4G+3; each lane
// owns tokens {lane, lane+32}. Thread: 8 independent in-order scalar fma.rn
// chains (2 tokens x 4 experts) — bitwise identical to all passing rounds.
// Crossbar law (calibrated R4/R8/R9): every shared-op costs ~4 cyc/warp, so
// minimize LDS count: per 4-dim group only 2 x-LDS.128 + 4 w-LDS.128 for
// 32 FMAs (5.33 FMA/LDS vs R9's 2.67).
// W layout: swg[G][d4*20 + k*4 + j] = W[4G+j][4*d4+k]  (pad-20 -> the
// staging STS.128 transpose is bank-conflict-free; compute reads broadcast).
// ---------------------------------------------------------------------------
#define K1T   64
#define TILE  64
#define CH    32
#define XP    36      // x pitch: 144B rows, conflict-free LDS.128
#define WG    10240   // floats per expert-group: 512 d4 * 20

__global__ void __launch_bounds__(K1T) k1_gemv(const float* __restrict__ x,
                                               const float* __restrict__ W)
{
    extern __shared__ float sm[];
    float* swg = sm;                 // [2][WG]        80 KB
    float* sx  = sm + 2 * WG;        // [2][TILE*XP]   18 KB

    const int tid  = threadIdx.x;
    const int lane = tid & 31;
    const int G    = tid >> 5;       // expert group (0: e0-3, 1: e4-7)
    const size_t rowBase = (size_t)blockIdx.x * TILE;

    // Stage W group G, transposed 4-expert-interleaved with pad-20 pitch.
    {
        const float4* W4 = reinterpret_cast<const float4*>(W);
        float* dst = swg + G * WG;
#pragma unroll 4
        for (int it = 0; it < 16; ++it) {
            int d4 = it * 32 + lane;
            float4 w0 = W4[(4 * G + 0) * 512 + d4];
            float4 w1 = W4[(4 * G + 1) * 512 + d4];
            float4 w2 = W4[(4 * G + 2) * 512 + d4];
            float4 w3 = W4[(4 * G + 3) * 512 + d4];
            float4* dp = reinterpret_cast<float4*>(dst + d4 * 20);
            dp[0] = make_float4(w0.x, w1.x, w2.x, w3.x);
            dp[1] = make_float4(w0.y, w1.y, w2.y, w3.y);
            dp[2] = make_float4(w0.z, w1.z, w2.z, w3.z);
            dp[3] = make_float4(w0.w, w1.w, w2.w, w3.w);
        }
    }

    // x staging: 64 tokens x 32 dims = 512 float4/chunk; 8 per thread.
    int rr[8], cc[8];
#pragma unroll
    for (int k = 0; k < 8; ++k) {
        int idx = tid + k * K1T;
        rr[k] = idx >> 3;
        cc[k] = idx & 7;
    }

    const float* xb = x + rowBase * DIMX;

    float4 pf[8];
#pragma unroll
    for (int k = 0; k < 8; ++k)
        pf[k] = *reinterpret_cast<const float4*>(xb + (size_t)rr[k] * DIMX + cc[k] * 4);
#pragma unroll
    for (int k = 0; k < 8; ++k)
        *reinterpret_cast<float4*>(&sx[rr[k] * XP + cc[k] * 4]) = pf[k];
#pragma unroll
    for (int k = 0; k < 8; ++k)
        pf[k] = *reinterpret_cast<const float4*>(xb + (size_t)rr[k] * DIMX + CH + cc[k] * 4);

    float a00 = 0.f, a01 = 0.f, a02 = 0.f, a03 = 0.f;   // token0 x experts 4G+0..3
    float a10 = 0.f, a11 = 0.f, a12 = 0.f, a13 = 0.f;   // token1 x experts 4G+0..3

    __syncthreads();   // buf0 + swg staged

    const float* wb0 = swg + G * WG;

    for (int ch = 0; ch < DIMX / CH; ++ch) {
        const int cur = ch & 1;

        if (ch + 1 < DIMX / CH) {
#pragma unroll
            for (int k = 0; k < 8; ++k)
                *reinterpret_cast<float4*>(
                    &sx[(cur ^ 1) * (TILE * XP) + rr[k] * XP + cc[k] * 4]) = pf[k];
        }
        if (ch + 2 < DIMX / CH) {
            const float* xc = xb + (ch + 2) * CH;
#pragma unroll
            for (int k = 0; k < 8; ++k)
                pf[k] = *reinterpret_cast<const float4*>(xc + (size_t)rr[k] * DIMX + cc[k] * 4);
        }

        const float* x0p = sx + cur * (TILE * XP) + lane * XP;
        const float* x1p = x0p + 32 * XP;
        const float* wb  = wb0 + ch * 160;         // 8 d4-groups x 20 floats
#pragma unroll
        for (int g = 0; g < 8; ++g) {
            float4 xv0 = *reinterpret_cast<const float4*>(x0p + g * 4);
            float4 xv1 = *reinterpret_cast<const float4*>(x1p + g * 4);
            const float* wg4 = wb + g * 20;
            float4 wk0 = *reinterpret_cast<const float4*>(wg4 + 0);   // dim 4g+0, e0..3
            float4 wk1 = *reinterpret_cast<const float4*>(wg4 + 4);   // dim 4g+1
            float4 wk2 = *reinterpret_cast<const float4*>(wg4 + 8);   // dim 4g+2
            float4 wk3 = *reinterpret_cast<const float4*>(wg4 + 12);  // dim 4g+3
            a00 = __fmaf_rn(xv0.x, wk0.x, a00); a01 = __fmaf_rn(xv0.x, wk0.y, a01);
            a02 = __fmaf_rn(xv0.x, wk0.z, a02); a03 = __fmaf_rn(xv0.x, wk0.w, a03);
            a10 = __fmaf_rn(xv1.x, wk0.x, a10); a11 = __fmaf_rn(xv1.x, wk0.y, a11);
            a12 = __fmaf_rn(xv1.x, wk0.z, a12); a13 = __fmaf_rn(xv1.x, wk0.w, a13);
            a00 = __fmaf_rn(xv0.y, wk1.x, a00); a01 = __fmaf_rn(xv0.y, wk1.y, a01);
            a02 = __fmaf_rn(xv0.y, wk1.z, a02); a03 = __fmaf_rn(xv0.y, wk1.w, a03);
            a10 = __fmaf_rn(xv1.y, wk1.x, a10); a11 = __fmaf_rn(xv1.y, wk1.y, a11);
            a12 = __fmaf_rn(xv1.y, wk1.z, a12); a13 = __fmaf_rn(xv1.y, wk1.w, a13);
            a00 = __fmaf_rn(xv0.z, wk2.x, a00); a01 = __fmaf_rn(xv0.z, wk2.y, a01);
            a02 = __fmaf_rn(xv0.z, wk2.z, a02); a03 = __fmaf_rn(xv0.z, wk2.w, a03);
            a10 = __fmaf_rn(xv1.z, wk2.x, a10); a11 = __fmaf_rn(xv1.z, wk2.y, a11);
            a12 = __fmaf_rn(xv1.z, wk2.z, a12); a13 = __fmaf_rn(xv1.z, wk2.w, a13);
            a00 = __fmaf_rn(xv0.w, wk3.x, a00); a01 = __fmaf_rn(xv0.w, wk3.y, a01);
            a02 = __fmaf_rn(xv0.w, wk3.z, a02); a03 = __fmaf_rn(xv0.w, wk3.w, a03);
            a10 = __fmaf_rn(xv1.w, wk3.x, a10); a11 = __fmaf_rn(xv1.w, wk3.y, a11);
            a12 = __fmaf_rn(xv1.w, wk3.z, a12); a13 = __fmaf_rn(xv1.w, wk3.w, a13);
        }
        __syncthreads();
    }

    // Emit 8 keys: tokens {t0, t1} x experts 4G..4G+3.
    const int t0 = (int)rowBase + lane;
    const int t1 = t0 + 32;
    float accs[8] = {a00, a01, a02, a03, a10, a11, a12, a13};
#pragma unroll
    for (int u = 0; u < 8; ++u) {
        int e = 4 * G + (u & 3);
        int t = (u < 4) ? t0 : t1;
        float em = __nv_expf(-accs[u]);
        float s  = __fdiv_rn(1.0f, __fadd_rn(1.0f, em));
        unsigned key = ~__float_as_uint(s);
        g_keys[e * T_TOKENS + t] = key;
        unsigned h = (unsigned)e * 16384u + (key >> 18);
        unsigned m = __match_any_sync(0xffffffffu, h);
        if ((int)lane == __ffs(m) - 1)
            atomicAdd(&g_hist[h], (unsigned)__popc(m));
    }
}

// ---------------------------------------------------------------------------
// Kernel 2: per-expert exact top-2048 (desc, ties -> lower index).
// 46-bit key K = (key32 << 14) | token. Level 0 = global 14-bit histogram;
// boundary-bin candidates warp-sorted (m<=64 common case) or 3 fallback
// radix levels; atomic-free collect; hybrid bitonic sort.
// ---------------------------------------------------------------------------
#define K2_THREADS 1024
#define HC         4
#define MASK46     ((1ull << 46) - 1)

__global__ void __launch_bounds__(K2_THREADS) k2_topk(float* __restrict__ out, int writeIdx)
{
    extern __shared__ unsigned char sm2[];
    unsigned int*        hist  = reinterpret_cast<unsigned int*>(sm2);
    unsigned int*        hscan = reinterpret_cast<unsigned int*>(sm2 + 65536);
    unsigned long long*  sel   = reinterpret_cast<unsigned long long*>(sm2 + 81920);
    unsigned long long*  cand  = reinterpret_cast<unsigned long long*>(sm2 + 98304);

    __shared__ unsigned int s_wsum[32];
    __shared__ unsigned long long s_pref;
    __shared__ unsigned long long s_mask;
    __shared__ unsigned long long s_kstar;
    __shared__ int          s_want;
    __shared__ int          s_bin;
    __shared__ unsigned int s_before;
    __shared__ int          s_exact;
    __shared__ int          s_n;

    const int e    = blockIdx.x;
    const int tid  = threadIdx.x;
    const unsigned lane = tid & 31;
    const int wid  = tid >> 5;

    unsigned kreg[16];
    {
        const unsigned* gk = g_keys + e * T_TOKENS;
#pragma unroll
        for (int r = 0; r < 16; ++r)
            kreg[r] = gk[tid + r * K2_THREADS];
    }

    if (tid == 0) { s_exact = 0; s_n = 0; }
    __syncthreads();

    // ---- Level 0: scan global 14-bit histogram (16 bins/thread) ----
    {
        const uint4* gh = reinterpret_cast<const uint4*>(g_hist + e * 16384);
        unsigned lsum = 0;
        uint4 u0 = gh[tid * 4 + 0], u1 = gh[tid * 4 + 1];
        uint4 u2 = gh[tid * 4 + 2], u3 = gh[tid * 4 + 3];
        lsum = u0.x + u0.y + u0.z + u0.w + u1.x + u1.y + u1.z + u1.w
             + u2.x + u2.y + u2.z + u2.w + u3.x + u3.y + u3.z + u3.w;
        unsigned si = lsum;
#pragma unroll
        for (int o = 1; o < 32; o <<= 1) {
            unsigned n = __shfl_up_sync(0xffffffffu, si, o);
            if (lane >= (unsigned)o) si += n;
        }
        if (lane == 31) s_wsum[wid] = si;
        __syncthreads();
        if (wid == 0) {
            unsigned w = s_wsum[lane];
            unsigned wi = w;
#pragma unroll
            for (int o = 1; o < 32; o <<= 1) {
                unsigned n = __shfl_up_sync(0xffffffffu, wi, o);
                if (lane >= (unsigned)o) wi += n;
            }
            s_wsum[lane] = wi - w;
        }
        __syncthreads();
        unsigned base = s_wsum[wid] + (si - lsum);
        if ((int)base < KSEL && (int)(base + lsum) >= KSEL) {
            const unsigned* gb = g_hist + e * 16384 + tid * 16;
            unsigned run = base;
            for (int j = 0; j < 16; ++j) {
                unsigned c = gb[j];
                if ((int)run < KSEL && (int)(run + c) >= KSEL) {
                    s_bin = tid * 16 + j;
                    s_before = run;
                    if ((int)(run + c) == KSEL) s_exact = 1;
                    break;
                }
                run += c;
            }
        }
        __syncthreads();
        if (tid == 0) {
            s_want = KSEL - (int)s_before;
            s_pref = (unsigned long long)(unsigned)s_bin << 32;
            s_mask = 0x3FFFull << 32;
        }
        __syncthreads();
    }

    unsigned long long Kstar;
    if (s_exact) {
        Kstar = s_pref | 0xFFFFFFFFull;
    } else {
        const unsigned binv = (unsigned)s_bin;
#pragma unroll
        for (int r = 0; r < 16; ++r) {
            bool c = ((kreg[r] >> 18) == binv);
            unsigned bal = __ballot_sync(0xffffffffu, c);
            int base = 0;
            if (lane == 0 && bal) base = atomicAdd(&s_n, __popc(bal));
            base = __shfl_sync(0xffffffffu, base, 0);
            if (c) {
                int pos = base + __popc(bal & ((1u << lane) - 1u));
                if (pos < 2048)
                    cand[pos] = ((unsigned long long)kreg[r] << 14)
                              | (unsigned)(tid + r * K2_THREADS);
            }
        }
        __syncthreads();
        const int m = s_n;
        const int want = s_want;

        if (m <= 64) {
            if (wid == 0) {
                unsigned long long a = (lane < (unsigned)m) ? cand[lane] : ~0ull;
                unsigned long long b = (lane + 32 < (unsigned)m) ? cand[lane + 32] : ~0ull;
                const int g0 = (int)lane, g1 = (int)lane + 32;
                for (int k = 2; k <= 64; k <<= 1) {
                    for (int j = k >> 1; j >= 1; j >>= 1) {
                        if (j == 32) {
                            bool asc = ((g0 & k) == 0);
                            if ((a > b) == asc) { unsigned long long t = a; a = b; b = t; }
                        } else {
                            unsigned long long pa = __shfl_xor_sync(0xffffffffu, a, j);
                            unsigned long long pb = __shfl_xor_sync(0xffffffffu, b, j);
                            bool lower = ((lane & (unsigned)j) == 0u);
                            bool ascA  = ((g0 & k) == 0);
                            bool ascB  = ((g1 & k) == 0);
                            unsigned long long amin = (a < pa) ? a : pa;
                            unsigned long long amax = (a < pa) ? pa : a;
                            unsigned long long bmin = (b < pb) ? b : pb;
                            unsigned long long bmax = (b < pb) ? pb : b;
                            a = (lower == ascA) ? amin : amax;
                            b = (lower == ascB) ? bmin : bmax;
                        }
                    }
                }
                int idx = want - 1;
                unsigned long long va = __shfl_sync(0xffffffffu, a, idx & 31);
                unsigned long long vb = __shfl_sync(0xffffffffu, b, idx & 31);
                if (lane == 0) s_kstar = (idx < 32) ? va : vb;
            }
            __syncthreads();
            Kstar = s_kstar;
        } else {
            const int shifts[3] = {20, 10, 0};
            const int nbits [3] = {12, 10, 10};
            for (int lvl = 0; lvl < 3; ++lvl) {
                const int shift = shifts[lvl];
                const int nb    = 1 << nbits[lvl];
                const int wantLoc              = s_want;
                const unsigned long long mask  = s_mask;
                const unsigned long long pref  = s_pref;

                for (int i = tid; i < HC * 4096; i += K2_THREADS) hist[i] = 0u;
                __syncthreads();

                unsigned int* myhist = hist + (wid & (HC - 1)) * 4096;
#pragma unroll
                for (int r = 0; r < 16; ++r) {
                    unsigned long long K = ((unsigned long long)kreg[r] << 14)
                                         | (unsigned)(tid + r * K2_THREADS);
                    bool mm = ((K & mask) == pref);
                    unsigned active = __ballot_sync(0xffffffffu, mm);
                    if (mm) {
                        int bin = (int)((K >> shift) & (unsigned)(nb - 1));
                        unsigned same = __match_any_sync(active, bin);
                        if ((int)lane == (__ffs(same) - 1))
                            atomicAdd(&myhist[bin], (unsigned)__popc(same));
                    }
                }
                __syncthreads();
                {
                    unsigned v[4];
                    unsigned sthr = 0;
#pragma unroll
                    for (int j = 0; j < 4; ++j) {
                        int b = 4 * tid + j;
                        unsigned t = 0;
#pragma unroll
                        for (int c = 0; c < HC; ++c) t += hist[c * 4096 + b];
                        v[j] = t; sthr += t;
                    }
                    unsigned si = sthr;
#pragma unroll
                    for (int o = 1; o < 32; o <<= 1) {
                        unsigned n = __shfl_up_sync(0xffffffffu, si, o);
                        if (lane >= (unsigned)o) si += n;
                    }
                    if (lane == 31) s_wsum[wid] = si;
                    __syncthreads();
                    if (wid == 0) {
                        unsigned w = s_wsum[lane];
                        unsigned wi = w;
#pragma unroll
                        for (int o = 1; o < 32; o <<= 1) {
                            unsigned n = __shfl_up_sync(0xffffffffu, wi, o);
                            if (lane >= (unsigned)o) wi += n;
                        }
                        s_wsum[lane] = wi - w;
                    }
                    __syncthreads();
                    unsigned run = s_wsum[wid] + (si - sthr);
#pragma unroll
                    for (int j = 0; j < 4; ++j) {
                        run += v[j];
                        hscan[4 * tid + j] = run;
                    }
                }
                __syncthreads();
                for (int i = tid; i < nb; i += K2_THREADS) {
                    unsigned c = hscan[i];
                    unsigned p = (i > 0) ? hscan[i - 1] : 0u;
                    if ((int)c >= wantLoc && (int)p < wantLoc) {
                        s_bin = i; s_before = p;
                        if ((int)c == wantLoc) s_exact = 1;
                    }
                }
                __syncthreads();
                if (tid == 0) {
                    s_want = wantLoc - (int)s_before;
                    s_pref = pref | ((unsigned long long)(unsigned)s_bin << shift);
                    s_mask = mask | ((unsigned long long)(unsigned)(nb - 1) << shift);
                }
                __syncthreads();
                if (s_exact) break;
            }
            Kstar = s_pref | (~s_mask & MASK46);
        }
    }

    // ---- Final collect (atomic-free two-pass) ----
    {
        int cw = 0;
#pragma unroll
        for (int r = 0; r < 16; ++r) {
            unsigned long long K = ((unsigned long long)kreg[r] << 14)
                                 | (unsigned)(tid + r * K2_THREADS);
            unsigned bal = __ballot_sync(0xffffffffu, K <= Kstar);
            cw += __popc(bal);
        }
        if (lane == 0) s_wsum[wid] = (unsigned)cw;
        __syncthreads();
        if (wid == 0) {
            unsigned w = s_wsum[lane];
            unsigned wi = w;
#pragma unroll
            for (int o = 1; o < 32; o <<= 1) {
                unsigned n = __shfl_up_sync(0xffffffffu, wi, o);
                if (lane >= (unsigned)o) wi += n;
            }
            s_wsum[lane] = wi - w;
        }
        __syncthreads();
        int base = (int)s_wsum[wid];
#pragma unroll
        for (int r = 0; r < 16; ++r) {
            unsigned long long K = ((unsigned long long)kreg[r] << 14)
                                 | (unsigned)(tid + r * K2_THREADS);
            bool take = (K <= Kstar);
            unsigned bal = __ballot_sync(0xffffffffu, take);
            if (take) {
                int pos = base + __popc(bal & ((1u << lane) - 1u));
                sel[pos] = K;
            }
            base += __popc(bal);
        }
    }
    __syncthreads();

    // ---- Hybrid bitonic sort ascending over sel[2048] ----
    const int g0 = (wid << 6) | (int)lane;
    const int g1 = g0 + 32;
    unsigned long long a = sel[g0];
    unsigned long long b = sel[g1];

    for (int k = 2; k <= KSEL; k <<= 1) {
        int j = k >> 1;
        if (j >= 64) {
            sel[g0] = a; sel[g1] = b;
            __syncthreads();
            for (; j >= 64; j >>= 1) {
                int i = ((tid & ~(j - 1)) << 1) | (tid & (j - 1));
                int l = i | j;
                unsigned long long u = sel[i];
                unsigned long long v = sel[l];
                bool asc = ((i & k) == 0);
                if ((u > v) == asc) { sel[i] = v; sel[l] = u; }
                __syncthreads();
            }
            a = sel[g0]; b = sel[g1];
        }
        for (; j >= 1; j >>= 1) {
            if (j == 32) {
                bool asc = ((g0 & k) == 0);
                if ((a > b) == asc) { unsigned long long t = a; a = b; b = t; }
            } else {
                unsigned long long pa = __shfl_xor_sync(0xffffffffu, a, j);
                unsigned long long pb = __shfl_xor_sync(0xffffffffu, b, j);
                bool lower = ((lane & (unsigned)j) == 0u);
                bool ascA  = ((g0 & k) == 0);
                bool ascB  = ((g1 & k) == 0);
                unsigned long long amin = (a < pa) ? a : pa;
                unsigned long long amax = (a < pa) ? pa : a;
                unsigned long long bmin = (b < pb) ? b : pb;
                unsigned long long bmax = (b < pb) ? pb : b;
                a = (lower == ascA) ? amin : amax;
                b = (lower == ascB) ? bmin : bmax;
            }
        }
    }

    // Re-zero this expert's g_hist slice (restores invariant for replay).
    {
        uint4 z = make_uint4(0u, 0u, 0u, 0u);
        uint4* gz = reinterpret_cast<uint4*>(g_hist + e * 16384);
        for (int i = tid; i < 16384 / 4; i += K2_THREADS) gz[i] = z;
    }

    {
        float scA = __uint_as_float(~(unsigned)(a >> 14));
        float scB = __uint_as_float(~(unsigned)(b >> 14));
        out[e * KSEL + g0] = scA;
        out[e * KSEL + g1] = scB;
        if (writeIdx) {
            out[NE * KSEL + e * KSEL + g0] = (float)(unsigned)(a & 0x3FFFu);
            out[NE * KSEL + e * KSEL + g1] = (float)(unsigned)(b & 0x3FFFu);
        }
    }
}

// ---------------------------------------------------------------------------
extern "C" void kernel_launch(void* const* d_in, const int* in_sizes, int n_in,
                              void* d_out, int out_size)
{
    const float* x = (const float*)d_in[0];   // [16384, 2048] f32
    const float* W = (const float*)d_in[1];   // [8, 2048] f32
    float* out = (float*)d_out;

    const int SMEM1 = (2 * WG + 2 * TILE * XP) * (int)sizeof(float);  // 100352
    const int SMEM2 = 65536 + 16384 + 16384 + 16384;                  // 114688

    cudaFuncSetAttribute(k1_gemv, cudaFuncAttributeMaxDynamicSharedMemorySize, SMEM1);
    cudaFuncSetAttribute(k2_topk, cudaFuncAttributeMaxDynamicSharedMemorySize, SMEM2);

    const int writeIdx = (out_size >= 2 * NE * KSEL) ? 1 : 0;

    k1_gemv<<<T_TOKENS / TILE, K1T, SMEM1>>>(x, W);
    k2_topk<<<NE, K2_THREADS, SMEM2>>>(out, writeIdx);
}